// round 10
// baseline (speedup 1.0000x reference)
#include <cuda_runtime.h>
#include <cuda_fp16.h>
#include <cstdint>
#include <cstddef>

// ---------------------------------------------------------------------------
// data [S=1024, B=256, I=2], W_ih [256,2], b_ih[256], W_hh [256,256],
// b_hh[256], lin_W [2,256], lin_b[2]; out = softmax(h @ lin_W^T + lin_b).
//
// R10 = R7 loop structure VERBATIM (two regressions proved it's a local
// optimum) + orthogonal overhead trims:
//   - incremental g_h / data pointers (no per-step 64-bit address math)
//   - hoisted slot/mbar base addresses (one IMAD per publish)
//   - head kernel: 2 rows/warp, uint4 loads (2x memory-level parallelism)
// ---------------------------------------------------------------------------

#define S_LEN    1024
#define BATCH    256
#define HID      256
#define NTHREADS 256

#define HROW   264                  // 128 | pad4 | 128 | pad4
#define HPBUF  (4*HROW)             // 4 batch rows
#define SMEM_FLOATS (2*HPBUF)       // 2112 floats = 8448 B

__device__ __half g_h[(size_t)S_LEN * BATCH * HID];   // 134 MB fp16 scratch

typedef unsigned long long u64;

__device__ __forceinline__ void fma2(u64& acc, u64 a, u64 b) {
    asm("fma.rn.f32x2 %0, %1, %2, %0;" : "+l"(acc) : "l"(a), "l"(b));
}
__device__ __forceinline__ u64 add2(u64 a, u64 b) {
    u64 r; asm("add.rn.f32x2 %0, %1, %2;" : "=l"(r) : "l"(a), "l"(b)); return r;
}
__device__ __forceinline__ float pairsum(u64 v) {
    return __uint_as_float((unsigned)(v & 0xffffffffull)) +
           __uint_as_float((unsigned)(v >> 32));
}
__device__ __forceinline__ float fast_tanh(float x) {
    float e = __expf(-2.0f * x);
    return __fdividef(1.0f - e, 1.0f + e);
}
__device__ __forceinline__ void mbar_wait(uint32_t mba, uint32_t par) {
    asm volatile(
        "{\n\t.reg .pred P;\n"
        "WL_%=:\n\t"
        "mbarrier.try_wait.parity.acquire.cluster.shared::cta.b64 P, [%0], %1, 0x989680;\n\t"
        "@P bra.uni WD_%=;\n\t"
        "bra.uni WL_%=;\n"
        "WD_%=:\n\t}"
        :: "r"(mba), "r"(par) : "memory");
}
__device__ __forceinline__ void st_async(uint32_t addr, uint32_t val, uint32_t mbar) {
    asm volatile("st.async.shared::cluster.mbarrier::complete_tx::bytes.u32 [%0], %1, [%2];"
                 :: "r"(addr), "r"(val), "r"(mbar) : "memory");
}

__global__ void __launch_bounds__(NTHREADS, 1) __cluster_dims__(2, 1, 1)
rnn_scan_kernel(const float* __restrict__ data,
                const float* __restrict__ W_ih,
                const float* __restrict__ b_ih,
                const float* __restrict__ W_hh,
                const float* __restrict__ b_hh)
{
    __shared__ __align__(16) float sm[SMEM_FLOATS];
    __shared__ __align__(8)  unsigned long long mb[4];   // [pair*2 + buf]

    const int tid = threadIdx.x;
    uint32_t rank;
    asm("mov.u32 %0, %%cluster_ctarank;" : "=r"(rank));
    const int g   = blockIdx.x >> 1;          // batch group of 4 rows
    const int hh  = tid >> 1;                 // column within half
    const int kc  = tid & 1;                  // k-half this thread reduces
    const int col = (int)rank * 128 + hh;     // global output column
    const int rowA = kc;                      // row finalized from pair0
    const int rowB = 2 + kc;                  // row finalized from pair1

    // ---- init: zero h buf0 ----
    for (int i = tid; i < HPBUF; i += NTHREADS) sm[i] = 0.0f;

    // ---- W_hh half-row -> 64 u64 registers ----
    u64 W[64];
    {
        const float* wp = W_hh + (size_t)col * HID + kc * 128;
        #pragma unroll
        for (int j = 0; j < 32; ++j) {
            ulonglong2 t = *(const ulonglong2*)(wp + 4 * j);
            W[2 * j] = t.x; W[2 * j + 1] = t.y;
        }
    }
    const float biasv = b_ih[col] + b_hh[col];
    const float wih0  = W_ih[col * 2 + 0];
    const float wih1  = W_ih[col * 2 + 1];

    uint32_t sm_u32, mb_u32;
    asm("{ .reg .u64 t; cvta.to.shared.u64 t, %1; cvt.u32.u64 %0, t; }"
        : "=r"(sm_u32) : "l"(sm));
    asm("{ .reg .u64 t; cvta.to.shared.u64 t, %1; cvt.u32.u64 %0, t; }"
        : "=r"(mb_u32) : "l"(mb));
    uint32_t self_sm, self_mb, peer_sm, peer_mb;
    asm("mapa.shared::cluster.u32 %0, %1, %2;" : "=r"(self_sm) : "r"(sm_u32), "r"(rank));
    asm("mapa.shared::cluster.u32 %0, %1, %2;" : "=r"(self_mb) : "r"(mb_u32), "r"(rank));
    asm("mapa.shared::cluster.u32 %0, %1, %2;" : "=r"(peer_sm) : "r"(sm_u32), "r"(rank ^ 1u));
    asm("mapa.shared::cluster.u32 %0, %1, %2;" : "=r"(peer_mb) : "r"(mb_u32), "r"(rank ^ 1u));

    // count = 1: only tid0's expect_tx arrive; everything else is tx bytes
    if (tid < 4)
        asm volatile("mbarrier.init.shared.b64 [%0], %1;"
                     :: "r"(mb_u32 + (uint32_t)tid * 8u), "r"(1u) : "memory");
    __syncthreads();
    // peer mbars + zeroed h must be live before any st.async traffic
    asm volatile("barrier.cluster.arrive.aligned;" ::: "memory");
    asm volatile("barrier.cluster.wait.aligned;"   ::: "memory");

    // x-term constants for step 0: x0 = [1, 0]
    float cA = wih0 + biasv;
    float cB = wih0 + biasv;

    // hoisted per-thread bases (loop adds are single IMAD/IADD)
    const uint32_t slotBaseA = (uint32_t)(rowA * HROW + (int)rank * 132 + hh) * 4u;
    const uint32_t slotBaseB = (uint32_t)(rowB * HROW + (int)rank * 132 + hh) * 4u;
    __half* ghA = g_h + (size_t)(g * 4 + rowA) * HID + col;
    __half* ghB = g_h + (size_t)(g * 4 + rowB) * HID + col;
    const float* xpA = data + (g * 4 + rowA) * 2;   // x[s+1] row A source
    const float* xpB = data + (g * 4 + rowB) * 2;

    for (int s = 0; s < S_LEN; ++s) {
        const int cur = s & 1, nxt = cur ^ 1;
        const uint32_t par = (uint32_t)(((s - 1) >> 1) & 1);

        // arm both pair-barriers for buf[nxt] (2048B of st.async each)
        if (tid == 0) {
            asm volatile("mbarrier.arrive.expect_tx.shared.b64 _, [%0], %1;"
                         :: "r"(mb_u32 + (uint32_t)(0 + nxt) * 8u), "r"(2048u) : "memory");
            asm volatile("mbarrier.arrive.expect_tx.shared.b64 _, [%0], %1;"
                         :: "r"(mb_u32 + (uint32_t)(2 + nxt) * 8u), "r"(2048u) : "memory");
        }

        // prefetch x for step s+1 (x[s+1] = data[s]) into registers
        float2 xnA, xnB;
        const bool havex = (s < S_LEN - 1);
        if (havex) {
            xnA = *(const float2*)xpA;
            xnB = *(const float2*)xpB;
        }

        // ======== phase 0: wait + FMA rows 0,1 ========
        if (s > 0) mbar_wait(mb_u32 + (uint32_t)(0 + cur) * 8u, par);
        const float* hb0 = sm + cur * HPBUF + 0 * HROW + kc * 132;
        u64 a0 = 0, a1 = 0, b0 = 0, b1 = 0;
        #pragma unroll
        for (int j = 0; j < 32; ++j) {
            const int k = 4 * j;
            ulonglong2 h0 = *(const ulonglong2*)(hb0 + k);
            ulonglong2 h1 = *(const ulonglong2*)(hb0 + HROW + k);
            fma2(a0, W[2*j], h0.x); fma2(a1, W[2*j+1], h0.y);
            fma2(b0, W[2*j], h1.x); fma2(b1, W[2*j+1], h1.y);
        }

        // ---- tail0 (row kc): finalize + publish EARLY (R8 lesson) ----
        {
            float p0 = pairsum(add2(a0, a1));
            float p1 = pairsum(add2(b0, b1));
            float q0 = __shfl_xor_sync(0xffffffffu, p0, 1);
            float q1 = __shfl_xor_sync(0xffffffffu, p1, 1);
            float tA = (kc == 0) ? (p0 + q0) : (p1 + q1);
            float vA = fast_tanh(cA + tA);
            const uint32_t slotA = slotBaseA + (uint32_t)nxt * (HPBUF * 4u);
            const uint32_t mbA   = (uint32_t)(0 + nxt) * 8u;
            const uint32_t vvA   = __float_as_uint(vA);
            st_async(self_sm + slotA, vvA, self_mb + mbA);
            st_async(peer_sm + slotA, vvA, peer_mb + mbA);
            *ghA = __float2half(vA);
        }

        // ======== phase 1: wait + FMA rows 2,3 ========
        if (s > 0) mbar_wait(mb_u32 + (uint32_t)(2 + cur) * 8u, par);
        const float* hb1 = sm + cur * HPBUF + 2 * HROW + kc * 132;
        u64 c0 = 0, c1 = 0, d0 = 0, d1 = 0;
        #pragma unroll
        for (int j = 0; j < 32; ++j) {
            const int k = 4 * j;
            ulonglong2 h2 = *(const ulonglong2*)(hb1 + k);
            ulonglong2 h3 = *(const ulonglong2*)(hb1 + HROW + k);
            fma2(c0, W[2*j], h2.x); fma2(c1, W[2*j+1], h2.y);
            fma2(d0, W[2*j], h3.x); fma2(d1, W[2*j+1], h3.y);
        }

        // ---- tail1 (row 2+kc) ----
        {
            float p2 = pairsum(add2(c0, c1));
            float p3 = pairsum(add2(d0, d1));
            float q2 = __shfl_xor_sync(0xffffffffu, p2, 1);
            float q3 = __shfl_xor_sync(0xffffffffu, p3, 1);
            float tB = (kc == 0) ? (p2 + q2) : (p3 + q3);
            float vB = fast_tanh(cB + tB);
            const uint32_t slotB = slotBaseB + (uint32_t)nxt * (HPBUF * 4u);
            const uint32_t mbB   = (uint32_t)(2 + nxt) * 8u;
            const uint32_t vvB   = __float_as_uint(vB);
            st_async(self_sm + slotB, vvB, self_mb + mbB);
            st_async(peer_sm + slotB, vvB, peer_mb + mbB);
            *ghB = __float2half(vB);
        }

        // trailing independent work (fills tail1's latency shadow)
        ghA += BATCH * HID;
        ghB += BATCH * HID;
        xpA += BATCH * 2;
        xpB += BATCH * 2;
        if (havex) {
            cA = fmaf(xnA.x, wih0, fmaf(xnA.y, wih1, biasv));
            cB = fmaf(xnB.x, wih0, fmaf(xnB.y, wih1, biasv));
        }
    }

    // keep smem/mbars alive until peer's trailing async traffic drains
    asm volatile("barrier.cluster.arrive.aligned;" ::: "memory");
    asm volatile("barrier.cluster.wait.aligned;"   ::: "memory");
}

// ---------------------------------------------------------------------------
// Head: logits = h @ lin_W^T + lin_b, softmax over I=2.
// One warp per TWO (s,b) rows; uint4 (8-half) loads, both issued up front.
// ---------------------------------------------------------------------------
__global__ void __launch_bounds__(256)
rnn_head_kernel(const float* __restrict__ lin_W,
                const float* __restrict__ lin_b,
                float* __restrict__ out)
{
    __shared__ float w0s[HID], w1s[HID], lbs[2];
    const int tid = threadIdx.x;
    if (tid < HID) { w0s[tid] = lin_W[tid]; w1s[tid] = lin_W[HID + tid]; }
    if (tid < 2)   lbs[tid] = lin_b[tid];
    __syncthreads();

    const int lane = tid & 31;
    const size_t sb0 = (size_t)blockIdx.x * 16 + (tid >> 5) * 2;

    // both rows' loads issued back-to-back (2x MLP)
    uint4 v0 = *(const uint4*)(g_h + sb0 * HID + lane * 8);
    uint4 v1 = *(const uint4*)(g_h + (sb0 + 1) * HID + lane * 8);

    float4 wa0 = *(const float4*)(w0s + lane * 8);
    float4 wa1 = *(const float4*)(w0s + lane * 8 + 4);
    float4 wb0 = *(const float4*)(w1s + lane * 8);
    float4 wb1 = *(const float4*)(w1s + lane * 8 + 4);

    #pragma unroll
    for (int r = 0; r < 2; ++r) {
        uint4 v = r ? v1 : v0;
        float2 h0 = __half22float2(*(const __half2*)&v.x);
        float2 h1 = __half22float2(*(const __half2*)&v.y);
        float2 h2 = __half22float2(*(const __half2*)&v.z);
        float2 h3 = __half22float2(*(const __half2*)&v.w);

        float acc0 = h0.x*wa0.x + h0.y*wa0.y + h1.x*wa0.z + h1.y*wa0.w
                   + h2.x*wa1.x + h2.y*wa1.y + h3.x*wa1.z + h3.y*wa1.w;
        float acc1 = h0.x*wb0.x + h0.y*wb0.y + h1.x*wb0.z + h1.y*wb0.w
                   + h2.x*wb1.x + h2.y*wb1.y + h3.x*wb1.z + h3.y*wb1.w;

        #pragma unroll
        for (int m = 16; m; m >>= 1) {
            acc0 += __shfl_xor_sync(0xffffffffu, acc0, m);
            acc1 += __shfl_xor_sync(0xffffffffu, acc1, m);
        }
        if (lane == 0) {
            float l0 = acc0 + lbs[0], l1 = acc1 + lbs[1];
            float mx = fmaxf(l0, l1);
            float e0 = expf(l0 - mx), e1 = expf(l1 - mx);
            float inv = 1.0f / (e0 + e1);
            float2 o; o.x = e0 * inv; o.y = e1 * inv;
            *(float2*)(out + (sb0 + r) * 2) = o;
        }
    }
}

// ---------------------------------------------------------------------------
extern "C" void kernel_launch(void* const* d_in, const int* in_sizes, int n_in,
                              void* d_out, int out_size)
{
    (void)in_sizes; (void)n_in; (void)out_size;
    const float* data  = (const float*)d_in[0];
    const float* W_ih  = (const float*)d_in[1];
    const float* b_ih  = (const float*)d_in[2];
    const float* W_hh  = (const float*)d_in[3];
    const float* b_hh  = (const float*)d_in[4];
    const float* lin_W = (const float*)d_in[5];
    const float* lin_b = (const float*)d_in[6];
    float* out = (float*)d_out;

    rnn_scan_kernel<<<128, NTHREADS>>>(data, W_ih, b_ih, W_hh, b_hh);
    // 262144 (s,b) rows, 2 per warp, 8 warps per block -> 16384 blocks
    rnn_head_kernel<<<(S_LEN * BATCH) / 16, 256>>>(lin_W, lin_b, out);
}

// round 11
// speedup vs baseline: 1.3891x; 1.3891x over previous
#include <cuda_runtime.h>
#include <cuda_fp16.h>
#include <cstdint>
#include <cstddef>

// ---------------------------------------------------------------------------
// data [S=1024, B=256, I=2], W_ih [256,2], b_ih[256], W_hh [256,256],
// b_hh[256], lin_W [2,256], lin_b[2]; out = softmax(h @ lin_W^T + lin_b).
//
// R11 = R7 scan kernel BYTE-IDENTICAL (best measured: 1292 us; R8/R9/R10
// restructurings all regressed to ~1700+ -> schedule-sensitive, locked)
//     + R10 head kernel (2 rows/warp, uint4 loads; verified 48.8->45.0 us).
// ---------------------------------------------------------------------------

#define S_LEN    1024
#define BATCH    256
#define HID      256
#define NTHREADS 256

#define HROW   264                  // 128 | pad4 | 128 | pad4
#define HPBUF  (4*HROW)             // 4 batch rows
#define SMEM_FLOATS (2*HPBUF)       // 2112 floats = 8448 B

__device__ __half g_h[(size_t)S_LEN * BATCH * HID];   // 134 MB fp16 scratch

typedef unsigned long long u64;

__device__ __forceinline__ void fma2(u64& acc, u64 a, u64 b) {
    asm("fma.rn.f32x2 %0, %1, %2, %0;" : "+l"(acc) : "l"(a), "l"(b));
}
__device__ __forceinline__ u64 add2(u64 a, u64 b) {
    u64 r; asm("add.rn.f32x2 %0, %1, %2;" : "=l"(r) : "l"(a), "l"(b)); return r;
}
__device__ __forceinline__ float pairsum(u64 v) {
    return __uint_as_float((unsigned)(v & 0xffffffffull)) +
           __uint_as_float((unsigned)(v >> 32));
}
__device__ __forceinline__ float fast_tanh(float x) {
    float e = __expf(-2.0f * x);
    return __fdividef(1.0f - e, 1.0f + e);
}
__device__ __forceinline__ void mbar_wait(uint32_t mba, uint32_t par) {
    asm volatile(
        "{\n\t.reg .pred P;\n"
        "WL_%=:\n\t"
        "mbarrier.try_wait.parity.acquire.cluster.shared::cta.b64 P, [%0], %1, 0x989680;\n\t"
        "@P bra.uni WD_%=;\n\t"
        "bra.uni WL_%=;\n"
        "WD_%=:\n\t}"
        :: "r"(mba), "r"(par) : "memory");
}

__global__ void __launch_bounds__(NTHREADS, 1) __cluster_dims__(2, 1, 1)
rnn_scan_kernel(const float* __restrict__ data,
                const float* __restrict__ W_ih,
                const float* __restrict__ b_ih,
                const float* __restrict__ W_hh,
                const float* __restrict__ b_hh)
{
    __shared__ __align__(16) float sm[SMEM_FLOATS];
    __shared__ __align__(8)  unsigned long long mb[4];   // [pair*2 + buf]

    const int tid = threadIdx.x;
    uint32_t rank;
    asm("mov.u32 %0, %%cluster_ctarank;" : "=r"(rank));
    const int g   = blockIdx.x >> 1;          // batch group of 4 rows
    const int hh  = tid >> 1;                 // column within half
    const int kc  = tid & 1;                  // k-half this thread reduces
    const int col = (int)rank * 128 + hh;     // global output column
    const int rowA = kc;                      // row finalized in phase A
    const int rowB = 2 + kc;                  // row finalized in phase B

    // ---- init: zero h buf0 ----
    for (int i = tid; i < HPBUF; i += NTHREADS) sm[i] = 0.0f;

    // ---- W_hh half-row -> 64 u64 registers ----
    u64 W[64];
    {
        const float* wp = W_hh + (size_t)col * HID + kc * 128;
        #pragma unroll
        for (int j = 0; j < 32; ++j) {
            ulonglong2 t = *(const ulonglong2*)(wp + 4 * j);
            W[2 * j] = t.x; W[2 * j + 1] = t.y;
        }
    }
    const float biasv = b_ih[col] + b_hh[col];
    const float wih0  = W_ih[col * 2 + 0];
    const float wih1  = W_ih[col * 2 + 1];

    uint32_t sm_u32, mb_u32;
    asm("{ .reg .u64 t; cvta.to.shared.u64 t, %1; cvt.u32.u64 %0, t; }"
        : "=r"(sm_u32) : "l"(sm));
    asm("{ .reg .u64 t; cvta.to.shared.u64 t, %1; cvt.u32.u64 %0, t; }"
        : "=r"(mb_u32) : "l"(mb));
    uint32_t self_sm, self_mb, peer_sm, peer_mb;
    asm("mapa.shared::cluster.u32 %0, %1, %2;"
        : "=r"(self_sm) : "r"(sm_u32), "r"(rank));
    asm("mapa.shared::cluster.u32 %0, %1, %2;"
        : "=r"(self_mb) : "r"(mb_u32), "r"(rank));
    asm("mapa.shared::cluster.u32 %0, %1, %2;"
        : "=r"(peer_sm) : "r"(sm_u32), "r"(rank ^ 1u));
    asm("mapa.shared::cluster.u32 %0, %1, %2;"
        : "=r"(peer_mb) : "r"(mb_u32), "r"(rank ^ 1u));

    // count = 1: only tid0's expect_tx arrive; everything else is tx bytes
    if (tid < 4)
        asm volatile("mbarrier.init.shared.b64 [%0], %1;"
                     :: "r"(mb_u32 + (uint32_t)tid * 8u), "r"(1u) : "memory");
    __syncthreads();
    // peer mbars + zeroed h must be live before any st.async traffic
    asm volatile("barrier.cluster.arrive.aligned;" ::: "memory");
    asm volatile("barrier.cluster.wait.aligned;"   ::: "memory");

    // x-term constants for step 0: x0 = [1, 0]
    float cA = wih0 + biasv;
    float cB = wih0 + biasv;

    for (int s = 0; s < S_LEN; ++s) {
        const int cur = s & 1, nxt = cur ^ 1;
        const uint32_t par = (uint32_t)(((s - 1) >> 1) & 1);

        // arm both pair-barriers for buf[nxt] (2048B of st.async each)
        if (tid == 0) {
            asm volatile("mbarrier.arrive.expect_tx.shared.b64 _, [%0], %1;"
                         :: "r"(mb_u32 + (uint32_t)(0 + nxt) * 8u), "r"(2048u) : "memory");
            asm volatile("mbarrier.arrive.expect_tx.shared.b64 _, [%0], %1;"
                         :: "r"(mb_u32 + (uint32_t)(2 + nxt) * 8u), "r"(2048u) : "memory");
        }

        // prefetch x for step s+1 (x[s+1] = data[s]) into registers
        float2 xnA, xnB;
        const bool havex = (s < S_LEN - 1);
        if (havex) {
            const float* xb = data + (size_t)s * BATCH * 2;
            xnA = *(const float2*)(xb + (g * 4 + rowA) * 2);
            xnB = *(const float2*)(xb + (g * 4 + rowB) * 2);
        }

        #pragma unroll
        for (int p = 0; p < 2; ++p) {
            // gate: rows 2p,2p+1 of h_s fully present (self + peer st.async)
            if (s > 0) mbar_wait(mb_u32 + (uint32_t)(p * 2 + cur) * 8u, par);

            // ---- FMA rows 2p, 2p+1 over own k-half ----
            const float* hb = sm + cur * HPBUF + p * 2 * HROW + kc * 132;
            u64 a0 = 0, a1 = 0, b0 = 0, b1 = 0;
            #pragma unroll
            for (int j = 0; j < 32; ++j) {
                const int k = 4 * j;
                ulonglong2 h0 = *(const ulonglong2*)(hb + k);
                ulonglong2 h1 = *(const ulonglong2*)(hb + HROW + k);
                fma2(a0, W[2*j], h0.x); fma2(a1, W[2*j+1], h0.y);
                fma2(b0, W[2*j], h1.x); fma2(b1, W[2*j+1], h1.y);
            }
            float p0 = pairsum(add2(a0, a1));   // partial, row 2p
            float p1 = pairsum(add2(b0, b1));   // partial, row 2p+1

            // cross-k-half reduction with partner lane (lane^1, same column)
            float q0 = __shfl_xor_sync(0xffffffffu, p0, 1);
            float q1 = __shfl_xor_sync(0xffffffffu, p1, 1);
            float t  = (kc == 0) ? (p0 + q0) : (p1 + q1);
            float v  = fast_tanh(((p == 0) ? cA : cB) + t);

            // ---- publish row (2p + kc) of h_{s+1}: self + peer st.async ----
            const int row = 2 * p + kc;
            const uint32_t slot =
                (uint32_t)(nxt * HPBUF + row * HROW + (int)rank * 132 + hh) * 4u;
            const uint32_t mbo = (uint32_t)(p * 2 + nxt) * 8u;
            const uint32_t vv  = __float_as_uint(v);
            asm volatile("st.async.shared::cluster.mbarrier::complete_tx::bytes.u32 [%0], %1, [%2];"
                         :: "r"(self_sm + slot), "r"(vv), "r"(self_mb + mbo) : "memory");
            asm volatile("st.async.shared::cluster.mbarrier::complete_tx::bytes.u32 [%0], %1, [%2];"
                         :: "r"(peer_sm + slot), "r"(vv), "r"(peer_mb + mbo) : "memory");

            // off the critical path: persist for the head kernel
            g_h[((size_t)s * BATCH + g * 4 + row) * HID + col] = __float2half(v);
        }

        // x-terms for step s+1 (independent math; hidden under the loop)
        if (havex) {
            cA = fmaf(xnA.x, wih0, fmaf(xnA.y, wih1, biasv));
            cB = fmaf(xnB.x, wih0, fmaf(xnB.y, wih1, biasv));
        }
    }

    // keep smem/mbars alive until peer's trailing async traffic drains
    asm volatile("barrier.cluster.arrive.aligned;" ::: "memory");
    asm volatile("barrier.cluster.wait.aligned;"   ::: "memory");
}

// ---------------------------------------------------------------------------
// Head: logits = h @ lin_W^T + lin_b, softmax over I=2.
// One warp per TWO (s,b) rows; uint4 (8-half) loads, both issued up front.
// ---------------------------------------------------------------------------
__global__ void __launch_bounds__(256)
rnn_head_kernel(const float* __restrict__ lin_W,
                const float* __restrict__ lin_b,
                float* __restrict__ out)
{
    __shared__ float w0s[HID], w1s[HID], lbs[2];
    const int tid = threadIdx.x;
    if (tid < HID) { w0s[tid] = lin_W[tid]; w1s[tid] = lin_W[HID + tid]; }
    if (tid < 2)   lbs[tid] = lin_b[tid];
    __syncthreads();

    const int lane = tid & 31;
    const size_t sb0 = (size_t)blockIdx.x * 16 + (tid >> 5) * 2;

    // both rows' loads issued back-to-back (2x MLP)
    uint4 v0 = *(const uint4*)(g_h + sb0 * HID + lane * 8);
    uint4 v1 = *(const uint4*)(g_h + (sb0 + 1) * HID + lane * 8);

    float4 wa0 = *(const float4*)(w0s + lane * 8);
    float4 wa1 = *(const float4*)(w0s + lane * 8 + 4);
    float4 wb0 = *(const float4*)(w1s + lane * 8);
    float4 wb1 = *(const float4*)(w1s + lane * 8 + 4);

    #pragma unroll
    for (int r = 0; r < 2; ++r) {
        uint4 v = r ? v1 : v0;
        float2 h0 = __half22float2(*(const __half2*)&v.x);
        float2 h1 = __half22float2(*(const __half2*)&v.y);
        float2 h2 = __half22float2(*(const __half2*)&v.z);
        float2 h3 = __half22float2(*(const __half2*)&v.w);

        float acc0 = h0.x*wa0.x + h0.y*wa0.y + h1.x*wa0.z + h1.y*wa0.w
                   + h2.x*wa1.x + h2.y*wa1.y + h3.x*wa1.z + h3.y*wa1.w;
        float acc1 = h0.x*wb0.x + h0.y*wb0.y + h1.x*wb0.z + h1.y*wb0.w
                   + h2.x*wb1.x + h2.y*wb1.y + h3.x*wb1.z + h3.y*wb1.w;

        #pragma unroll
        for (int m = 16; m; m >>= 1) {
            acc0 += __shfl_xor_sync(0xffffffffu, acc0, m);
            acc1 += __shfl_xor_sync(0xffffffffu, acc1, m);
        }
        if (lane == 0) {
            float l0 = acc0 + lbs[0], l1 = acc1 + lbs[1];
            float mx = fmaxf(l0, l1);
            float e0 = expf(l0 - mx), e1 = expf(l1 - mx);
            float inv = 1.0f / (e0 + e1);
            float2 o; o.x = e0 * inv; o.y = e1 * inv;
            *(float2*)(out + (sb0 + r) * 2) = o;
        }
    }
}

// ---------------------------------------------------------------------------
extern "C" void kernel_launch(void* const* d_in, const int* in_sizes, int n_in,
                              void* d_out, int out_size)
{
    (void)in_sizes; (void)n_in; (void)out_size;
    const float* data  = (const float*)d_in[0];
    const float* W_ih  = (const float*)d_in[1];
    const float* b_ih  = (const float*)d_in[2];
    const float* W_hh  = (const float*)d_in[3];
    const float* b_hh  = (const float*)d_in[4];
    const float* lin_W = (const float*)d_in[5];
    const float* lin_b = (const float*)d_in[6];
    float* out = (float*)d_out;

    rnn_scan_kernel<<<128, NTHREADS>>>(data, W_ih, b_ih, W_hh, b_hh);
    // 262144 (s,b) rows, 2 per warp, 8 warps per block -> 16384 blocks
    rnn_head_kernel<<<(S_LEN * BATCH) / 16, 256>>>(lin_W, lin_b, out);
}